// round 1
// baseline (speedup 1.0000x reference)
#include <cuda_runtime.h>
#include <cuda_bf16.h>
#include <cstdint>

#define N_NODES 50000
#define N_EDGES 800000
#define CH 128

// ---------------- device scratch (no allocations allowed) ----------------
__device__ int   g_is64;
__device__ int   g_deg[N_NODES];
__device__ int   g_rowptr[N_NODES + 1];
__device__ int   g_cursor[N_NODES];
__device__ int   g_csr[N_EDGES];
__device__ float g_invdeg[N_NODES];
__device__ float g_bufA[(size_t)N_NODES * CH];
__device__ float g_bufB[(size_t)N_NODES * CH];
__device__ float g_agg [(size_t)N_NODES * CH];

// ---------------- small setup kernels ----------------
__global__ void zero_init_kernel() {
    int i = blockIdx.x * blockDim.x + threadIdx.x;
    if (i < N_NODES) { g_deg[i] = 0; g_cursor[i] = 0; }
}

// Detect whether edge_index is int64 or int32 on disk.
// If int64 (little endian, values in [0,50000)), every odd 32-bit word is 0.
__global__ void detect_kernel(const unsigned* __restrict__ w) {
    __shared__ int any32;
    if (threadIdx.x == 0) any32 = 0;
    __syncthreads();
    for (int i = threadIdx.x; i < 1024; i += blockDim.x) {
        if (w[2 * i + 1] != 0u) any32 = 1;  // benign race
    }
    __syncthreads();
    if (threadIdx.x == 0) g_is64 = any32 ? 0 : 1;
}

__device__ __forceinline__ int load_edge(const void* ei, int idx, int is64) {
    if (is64) return (int)((const long long*)ei)[idx];
    return ((const int*)ei)[idx];
}

__global__ void deg_kernel(const void* __restrict__ ei) {
    int e = blockIdx.x * blockDim.x + threadIdx.x;
    if (e >= N_EDGES) return;
    int is64 = g_is64;
    int d = load_edge(ei, N_EDGES + e, is64);
    atomicAdd(&g_deg[d], 1);
}

// Single-block exclusive scan of degrees -> rowptr, plus inv_deg.
__global__ void scan_kernel() {
    __shared__ int sums[1024];
    const int CHK = (N_NODES + 1023) / 1024;  // 49
    int t = threadIdx.x;
    int base = t * CHK;
    int s = 0;
    for (int i = 0; i < CHK; i++) {
        int idx = base + i;
        if (idx < N_NODES) s += g_deg[idx];
    }
    sums[t] = s;
    __syncthreads();
    for (int off = 1; off < 1024; off <<= 1) {
        int v = 0;
        if (t >= off) v = sums[t - off];
        __syncthreads();
        if (t >= off) sums[t] += v;
        __syncthreads();
    }
    int run = sums[t] - s;  // exclusive prefix for this chunk
    for (int i = 0; i < CHK; i++) {
        int idx = base + i;
        if (idx < N_NODES) {
            g_rowptr[idx] = run;
            int d = g_deg[idx];
            run += d;
            g_invdeg[idx] = (d > 0) ? (1.0f / (float)d) : 0.0f;
        }
    }
    if (t == 1023) g_rowptr[N_NODES] = sums[1023];
}

__global__ void fill_kernel(const void* __restrict__ ei) {
    int e = blockIdx.x * blockDim.x + threadIdx.x;
    if (e >= N_EDGES) return;
    int is64 = g_is64;
    int s = load_edge(ei, e, is64);
    int d = load_edge(ei, N_EDGES + e, is64);
    int pos = atomicAdd(&g_cursor[d], 1);
    g_csr[g_rowptr[d] + pos] = s;
}

// ---------------- aggregation: one warp per node, gather over CSR ----------------
__global__ void agg_kernel(const float* __restrict__ H, float* __restrict__ Agg) {
    int gt = blockIdx.x * blockDim.x + threadIdx.x;
    int node = gt >> 5;
    int lane = gt & 31;
    if (node >= N_NODES) return;
    int beg = g_rowptr[node];
    int end = g_rowptr[node + 1];
    float4 acc = make_float4(0.f, 0.f, 0.f, 0.f);
    for (int i = beg; i < end; i++) {
        int src = g_csr[i];  // broadcast load across warp
        float4 v = *(const float4*)(H + (size_t)src * CH + lane * 4);
        acc.x += v.x; acc.y += v.y; acc.z += v.z; acc.w += v.w;
    }
    float s = g_invdeg[node];
    acc.x *= s; acc.y *= s; acc.z *= s; acc.w *= s;
    *(float4*)(Agg + (size_t)node * CH + lane * 4) = acc;
}

// ---------------- fused dual GEMM: Out = relu(Agg@Wl + bl + H@Wr) ----------------
// BM=128 rows per block, N=K=128, 512 threads, both W matrices fully in SMEM.
#define GEMM_THREADS 512
#define GEMM_BM 128
#define GEMM_KC 32
#define GEMM_SMEM_BYTES ((2 * 128 * 128 + 2 * GEMM_BM * GEMM_KC) * 4)  // 160 KB

__global__ void __launch_bounds__(GEMM_THREADS, 1)
gemm_kernel(const float* __restrict__ Agg, const float* __restrict__ H,
            const float* __restrict__ Wl, const float* __restrict__ Wr,
            const float* __restrict__ bl, float* __restrict__ Out) {
    extern __shared__ float smem[];
    float* sWl = smem;                  // 128x128
    float* sWr = smem + 16384;          // 128x128
    float* sA  = smem + 32768;          // BM x KC
    float* sH  = sA + GEMM_BM * GEMM_KC;

    int tid = threadIdx.x;
    int row0 = blockIdx.x * GEMM_BM;
    int tx = tid & 31;   // column group: cols tx*4 .. tx*4+3
    int ty = tid >> 5;   // row group: rows ty*8 .. ty*8+7

    // stage weights (4096 float4 each)
    for (int i = tid; i < 4096; i += GEMM_THREADS) {
        ((float4*)sWl)[i] = ((const float4*)Wl)[i];
        ((float4*)sWr)[i] = ((const float4*)Wr)[i];
    }

    float acc[8][4];
#pragma unroll
    for (int r = 0; r < 8; r++)
#pragma unroll
        for (int j = 0; j < 4; j++) acc[r][j] = 0.f;

    for (int kc = 0; kc < 128; kc += GEMM_KC) {
        __syncthreads();  // protect sA/sH (also orders W-load on first iter)
        // load A/H chunk: BM rows x KC cols = 1024 float4 each
        for (int i = tid; i < 1024; i += GEMM_THREADS) {
            int r   = i >> 3;        // 8 float4 per row
            int kk4 = i & 7;
            int row = row0 + r;
            float4 va = make_float4(0.f, 0.f, 0.f, 0.f);
            float4 vh = va;
            if (row < N_NODES) {
                va = *(const float4*)(Agg + (size_t)row * CH + kc + kk4 * 4);
                vh = *(const float4*)(H   + (size_t)row * CH + kc + kk4 * 4);
            }
            ((float4*)sA)[i] = va;
            ((float4*)sH)[i] = vh;
        }
        __syncthreads();
#pragma unroll 8
        for (int kk = 0; kk < GEMM_KC; kk++) {
            float4 wl = *(const float4*)(sWl + (kc + kk) * 128 + tx * 4);
            float4 wr = *(const float4*)(sWr + (kc + kk) * 128 + tx * 4);
#pragma unroll
            for (int r = 0; r < 8; r++) {
                float a = sA[(ty * 8 + r) * GEMM_KC + kk];
                float h = sH[(ty * 8 + r) * GEMM_KC + kk];
                acc[r][0] += a * wl.x; acc[r][0] += h * wr.x;
                acc[r][1] += a * wl.y; acc[r][1] += h * wr.y;
                acc[r][2] += a * wl.z; acc[r][2] += h * wr.z;
                acc[r][3] += a * wl.w; acc[r][3] += h * wr.w;
            }
        }
    }

    float4 b = *(const float4*)(bl + tx * 4);
#pragma unroll
    for (int r = 0; r < 8; r++) {
        int row = row0 + ty * 8 + r;
        if (row < N_NODES) {
            float4 o;
            o.x = fmaxf(acc[r][0] + b.x, 0.f);
            o.y = fmaxf(acc[r][1] + b.y, 0.f);
            o.z = fmaxf(acc[r][2] + b.z, 0.f);
            o.w = fmaxf(acc[r][3] + b.w, 0.f);
            *(float4*)(Out + (size_t)row * CH + tx * 4) = o;
        }
    }
}

// ---------------- head: logits = H @ Wh + bh, one warp per node ----------------
__global__ void head_kernel(const float* __restrict__ H, const float* __restrict__ Wh,
                            const float* __restrict__ bh, float* __restrict__ out) {
    __shared__ float sWh[CH];
    if (threadIdx.x < CH) sWh[threadIdx.x] = Wh[threadIdx.x];
    __syncthreads();
    int gt = blockIdx.x * blockDim.x + threadIdx.x;
    int node = gt >> 5;
    int lane = gt & 31;
    if (node >= N_NODES) return;
    float4 h = *(const float4*)(H + (size_t)node * CH + lane * 4);
    float4 w = *(const float4*)(sWh + lane * 4);
    float s = h.x * w.x + h.y * w.y + h.z * w.z + h.w * w.w;
#pragma unroll
    for (int off = 16; off > 0; off >>= 1)
        s += __shfl_down_sync(0xFFFFFFFFu, s, off);
    if (lane == 0) out[node] = s + bh[0];
}

// ---------------- launch ----------------
extern "C" void kernel_launch(void* const* d_in, const int* in_sizes, int n_in,
                              void* d_out, int out_size) {
    const float* x  = (const float*)d_in[0];
    const void*  ei = d_in[1];
    const float* Wl[3] = {(const float*)d_in[2], (const float*)d_in[5], (const float*)d_in[8]};
    const float* Wr[3] = {(const float*)d_in[3], (const float*)d_in[6], (const float*)d_in[9]};
    const float* bl[3] = {(const float*)d_in[4], (const float*)d_in[7], (const float*)d_in[10]};
    const float* Wh = (const float*)d_in[11];
    const float* bh = (const float*)d_in[12];
    float* out = (float*)d_out;

    cudaFuncSetAttribute(gemm_kernel, cudaFuncAttributeMaxDynamicSharedMemorySize,
                         GEMM_SMEM_BYTES);

    void *pA, *pB, *pAgg;
    cudaGetSymbolAddress(&pA, g_bufA);
    cudaGetSymbolAddress(&pB, g_bufB);
    cudaGetSymbolAddress(&pAgg, g_agg);
    float* bufA = (float*)pA;
    float* bufB = (float*)pB;
    float* agg  = (float*)pAgg;

    // CSR build
    zero_init_kernel<<<(N_NODES + 255) / 256, 256>>>();
    detect_kernel<<<1, 256>>>((const unsigned*)ei);
    deg_kernel<<<(N_EDGES + 255) / 256, 256>>>(ei);
    scan_kernel<<<1, 1024>>>();
    fill_kernel<<<(N_EDGES + 255) / 256, 256>>>(ei);

    const int warp_grid = (N_NODES * 32 + 255) / 256;
    const int gemm_grid = (N_NODES + GEMM_BM - 1) / GEMM_BM;

    const float* Hin = x;
    float* layer_out[3] = {bufA, bufB, bufA};
    for (int l = 0; l < 3; l++) {
        agg_kernel<<<warp_grid, 256>>>(Hin, agg);
        gemm_kernel<<<gemm_grid, GEMM_THREADS, GEMM_SMEM_BYTES>>>(
            agg, Hin, Wl[l], Wr[l], bl[l], layer_out[l]);
        Hin = layer_out[l];
    }
    head_kernel<<<warp_grid, 256>>>(Hin, Wh, bh, out);
}

// round 2
// speedup vs baseline: 1.2333x; 1.2333x over previous
#include <cuda_runtime.h>
#include <cuda_bf16.h>
#include <cstdint>

#define N_NODES 50000
#define N_EDGES 800000
#define CH 128

#define SCAN_BLK 512
#define NSCAN_BLOCKS ((N_NODES + SCAN_BLK - 1) / SCAN_BLK)  // 98

// ---------------- device scratch (no allocations allowed) ----------------
__device__ int   g_is64;
__device__ int   g_deg[N_NODES];
__device__ int   g_rowptr[N_NODES + 1];
__device__ int   g_cursor[N_NODES];
__device__ int   g_csr[N_EDGES];
__device__ int   g_bsum[NSCAN_BLOCKS];
__device__ int   g_boff[NSCAN_BLOCKS];
__device__ float g_invdeg[N_NODES];
__device__ float g_bufA[(size_t)N_NODES * CH];
__device__ float g_bufB[(size_t)N_NODES * CH];
__device__ float g_agg [(size_t)N_NODES * CH];

// ---------------- packed f32x2 helpers ----------------
__device__ __forceinline__ void ffma2(unsigned long long& d, unsigned long long a,
                                      unsigned long long b) {
    asm("fma.rn.f32x2 %0, %1, %2, %0;" : "+l"(d) : "l"(a), "l"(b));
}
__device__ __forceinline__ unsigned long long pack2(float x) {
    unsigned long long r;
    asm("mov.b64 %0, {%1, %1};" : "=l"(r) : "f"(x));
    return r;
}
__device__ __forceinline__ float2 unpack2(unsigned long long v) {
    float2 f;
    asm("mov.b64 {%0, %1}, %2;" : "=f"(f.x), "=f"(f.y) : "l"(v));
    return f;
}

// ---------------- small setup kernels ----------------
__global__ void zero_init_kernel() {
    int i = blockIdx.x * blockDim.x + threadIdx.x;
    if (i < N_NODES) g_deg[i] = 0;
}

// Detect whether edge_index is int64 or int32 on disk.
// If int64 (little endian, values in [0,50000)), every odd 32-bit word is 0.
__global__ void detect_kernel(const unsigned* __restrict__ w) {
    __shared__ int any32;
    if (threadIdx.x == 0) any32 = 0;
    __syncthreads();
    for (int i = threadIdx.x; i < 1024; i += blockDim.x) {
        if (w[2 * i + 1] != 0u) any32 = 1;  // benign race
    }
    __syncthreads();
    if (threadIdx.x == 0) g_is64 = any32 ? 0 : 1;
}

__device__ __forceinline__ int load_edge(const void* ei, int idx, int is64) {
    if (is64) return (int)((const long long*)ei)[idx];
    return ((const int*)ei)[idx];
}

__global__ void deg_kernel(const void* __restrict__ ei) {
    int e = blockIdx.x * blockDim.x + threadIdx.x;
    if (e >= N_EDGES) return;
    int is64 = g_is64;
    int d = load_edge(ei, N_EDGES + e, is64);
    atomicAdd(&g_deg[d], 1);
}

// ---------------- 3-phase multi-block exclusive scan ----------------
__global__ void bsum_kernel() {
    int i = blockIdx.x * SCAN_BLK + threadIdx.x;
    int v = (i < N_NODES) ? g_deg[i] : 0;
    int lane = threadIdx.x & 31, wid = threadIdx.x >> 5;
    __shared__ int ws[SCAN_BLK / 32];
#pragma unroll
    for (int off = 16; off > 0; off >>= 1)
        v += __shfl_down_sync(0xFFFFFFFFu, v, off);
    if (lane == 0) ws[wid] = v;
    __syncthreads();
    if (wid == 0) {
        v = (lane < SCAN_BLK / 32) ? ws[lane] : 0;
#pragma unroll
        for (int off = 16; off > 0; off >>= 1)
            v += __shfl_down_sync(0xFFFFFFFFu, v, off);
        if (lane == 0) g_bsum[blockIdx.x] = v;
    }
}

__global__ void bscan_kernel() {  // 1 block, 128 threads (NSCAN_BLOCKS=98)
    __shared__ int s[128];
    int t = threadIdx.x;
    int v = (t < NSCAN_BLOCKS) ? g_bsum[t] : 0;
    s[t] = v;
    __syncthreads();
    for (int off = 1; off < 128; off <<= 1) {
        int u = 0;
        if (t >= off) u = s[t - off];
        __syncthreads();
        if (t >= off) s[t] += u;
        __syncthreads();
    }
    if (t < NSCAN_BLOCKS) g_boff[t] = s[t] - v;  // exclusive
    if (t == NSCAN_BLOCKS - 1) g_rowptr[N_NODES] = s[t];
}

__global__ void scatter_scan_kernel() {
    int i = blockIdx.x * SCAN_BLK + threadIdx.x;
    int lane = threadIdx.x & 31, wid = threadIdx.x >> 5;
    int d = (i < N_NODES) ? g_deg[i] : 0;
    // warp inclusive scan
    int incl = d;
#pragma unroll
    for (int off = 1; off < 32; off <<= 1) {
        int u = __shfl_up_sync(0xFFFFFFFFu, incl, off);
        if (lane >= off) incl += u;
    }
    __shared__ int wsum[SCAN_BLK / 32];
    __shared__ int wexcl[SCAN_BLK / 32];
    if (lane == 31) wsum[wid] = incl;
    __syncthreads();
    if (threadIdx.x == 0) {
        int run = 0;
#pragma unroll
        for (int w = 0; w < SCAN_BLK / 32; w++) { wexcl[w] = run; run += wsum[w]; }
    }
    __syncthreads();
    if (i < N_NODES) {
        int ex = incl - d + wexcl[wid] + g_boff[blockIdx.x];
        g_rowptr[i] = ex;
        g_cursor[i] = ex;
        g_invdeg[i] = (d > 0) ? (1.0f / (float)d) : 0.0f;
    }
}

__global__ void fill_kernel(const void* __restrict__ ei) {
    int e = blockIdx.x * blockDim.x + threadIdx.x;
    if (e >= N_EDGES) return;
    int is64 = g_is64;
    int s = load_edge(ei, e, is64);
    int d = load_edge(ei, N_EDGES + e, is64);
    int pos = atomicAdd(&g_cursor[d], 1);
    g_csr[pos] = s;
}

// ---------------- aggregation: one warp per node, gather over CSR ----------------
__global__ void agg_kernel(const float* __restrict__ H, float* __restrict__ Agg) {
    int gt = blockIdx.x * blockDim.x + threadIdx.x;
    int node = gt >> 5;
    int lane = gt & 31;
    if (node >= N_NODES) return;
    int beg = g_rowptr[node];
    int end = g_rowptr[node + 1];
    float4 acc = make_float4(0.f, 0.f, 0.f, 0.f);
    for (int i = beg; i < end; i++) {
        int src = g_csr[i];  // broadcast load across warp
        float4 v = *(const float4*)(H + (size_t)src * CH + lane * 4);
        acc.x += v.x; acc.y += v.y; acc.z += v.z; acc.w += v.w;
    }
    float s = g_invdeg[node];
    acc.x *= s; acc.y *= s; acc.z *= s; acc.w *= s;
    *(float4*)(Agg + (size_t)node * CH + lane * 4) = acc;
}

// ---------------- fused dual GEMM: Out = relu(Agg@Wl + bl + H@Wr) ----------------
// BM=128 rows per block, N=K=128, 512 threads, both W matrices fully in SMEM.
// Inner product via packed fma.rn.f32x2 (2 cols per accumulator register pair).
#define GEMM_THREADS 512
#define GEMM_BM 128
#define GEMM_KC 32
#define GEMM_SMEM_BYTES ((2 * 128 * 128 + 2 * GEMM_BM * GEMM_KC) * 4)  // 160 KB

__global__ void __launch_bounds__(GEMM_THREADS, 1)
gemm_kernel(const float* __restrict__ Agg, const float* __restrict__ H,
            const float* __restrict__ Wl, const float* __restrict__ Wr,
            const float* __restrict__ bl, float* __restrict__ Out) {
    extern __shared__ float smem[];
    float* sWl = smem;                  // 128x128
    float* sWr = smem + 16384;          // 128x128
    float* sA  = smem + 32768;          // BM x KC
    float* sH  = sA + GEMM_BM * GEMM_KC;

    int tid = threadIdx.x;
    int row0 = blockIdx.x * GEMM_BM;
    int tx = tid & 31;   // column group: cols tx*4 .. tx*4+3
    int ty = tid >> 5;   // row group: rows ty*8 .. ty*8+7

    // stage weights (4096 float4 each)
    for (int i = tid; i < 4096; i += GEMM_THREADS) {
        ((float4*)sWl)[i] = ((const float4*)Wl)[i];
        ((float4*)sWr)[i] = ((const float4*)Wr)[i];
    }

    unsigned long long acc[8][2];
#pragma unroll
    for (int r = 0; r < 8; r++) { acc[r][0] = 0ull; acc[r][1] = 0ull; }

    for (int kc = 0; kc < 128; kc += GEMM_KC) {
        __syncthreads();  // protect sA/sH (also orders W-load on first iter)
        // load A/H chunk: BM rows x KC cols = 1024 float4 each
        for (int i = tid; i < 1024; i += GEMM_THREADS) {
            int r   = i >> 3;        // 8 float4 per row
            int kk4 = i & 7;
            int row = row0 + r;
            float4 va = make_float4(0.f, 0.f, 0.f, 0.f);
            float4 vh = va;
            if (row < N_NODES) {
                va = *(const float4*)(Agg + (size_t)row * CH + kc + kk4 * 4);
                vh = *(const float4*)(H   + (size_t)row * CH + kc + kk4 * 4);
            }
            ((float4*)sA)[i] = va;
            ((float4*)sH)[i] = vh;
        }
        __syncthreads();
#pragma unroll
        for (int kk = 0; kk < GEMM_KC; kk += 4) {
            // W pairs for 4 consecutive k values, loaded pre-packed (2 cols per u64)
            ulonglong2 wl[4], wr[4];
#pragma unroll
            for (int j = 0; j < 4; j++) {
                wl[j] = *(const ulonglong2*)(sWl + (kc + kk + j) * 128 + tx * 4);
                wr[j] = *(const ulonglong2*)(sWr + (kc + kk + j) * 128 + tx * 4);
            }
#pragma unroll
            for (int r = 0; r < 8; r++) {
                float4 a4 = *(const float4*)(sA + (ty * 8 + r) * GEMM_KC + kk);
                float4 h4 = *(const float4*)(sH + (ty * 8 + r) * GEMM_KC + kk);
                unsigned long long a0 = pack2(a4.x), a1 = pack2(a4.y),
                                   a2 = pack2(a4.z), a3 = pack2(a4.w);
                unsigned long long h0 = pack2(h4.x), h1 = pack2(h4.y),
                                   h2 = pack2(h4.z), h3 = pack2(h4.w);
                ffma2(acc[r][0], a0, wl[0].x); ffma2(acc[r][1], a0, wl[0].y);
                ffma2(acc[r][0], h0, wr[0].x); ffma2(acc[r][1], h0, wr[0].y);
                ffma2(acc[r][0], a1, wl[1].x); ffma2(acc[r][1], a1, wl[1].y);
                ffma2(acc[r][0], h1, wr[1].x); ffma2(acc[r][1], h1, wr[1].y);
                ffma2(acc[r][0], a2, wl[2].x); ffma2(acc[r][1], a2, wl[2].y);
                ffma2(acc[r][0], h2, wr[2].x); ffma2(acc[r][1], h2, wr[2].y);
                ffma2(acc[r][0], a3, wl[3].x); ffma2(acc[r][1], a3, wl[3].y);
                ffma2(acc[r][0], h3, wr[3].x); ffma2(acc[r][1], h3, wr[3].y);
            }
        }
    }

    float4 b = *(const float4*)(bl + tx * 4);
#pragma unroll
    for (int r = 0; r < 8; r++) {
        int row = row0 + ty * 8 + r;
        if (row < N_NODES) {
            float2 p0 = unpack2(acc[r][0]);
            float2 p1 = unpack2(acc[r][1]);
            float4 o;
            o.x = fmaxf(p0.x + b.x, 0.f);
            o.y = fmaxf(p0.y + b.y, 0.f);
            o.z = fmaxf(p1.x + b.z, 0.f);
            o.w = fmaxf(p1.y + b.w, 0.f);
            *(float4*)(Out + (size_t)row * CH + tx * 4) = o;
        }
    }
}

// ---------------- head: logits = H @ Wh + bh, one warp per node ----------------
__global__ void head_kernel(const float* __restrict__ H, const float* __restrict__ Wh,
                            const float* __restrict__ bh, float* __restrict__ out) {
    __shared__ float sWh[CH];
    if (threadIdx.x < CH) sWh[threadIdx.x] = Wh[threadIdx.x];
    __syncthreads();
    int gt = blockIdx.x * blockDim.x + threadIdx.x;
    int node = gt >> 5;
    int lane = gt & 31;
    if (node >= N_NODES) return;
    float4 h = *(const float4*)(H + (size_t)node * CH + lane * 4);
    float4 w = *(const float4*)(sWh + lane * 4);
    float s = h.x * w.x + h.y * w.y + h.z * w.z + h.w * w.w;
#pragma unroll
    for (int off = 16; off > 0; off >>= 1)
        s += __shfl_down_sync(0xFFFFFFFFu, s, off);
    if (lane == 0) out[node] = s + bh[0];
}

// ---------------- launch ----------------
extern "C" void kernel_launch(void* const* d_in, const int* in_sizes, int n_in,
                              void* d_out, int out_size) {
    const float* x  = (const float*)d_in[0];
    const void*  ei = d_in[1];
    const float* Wl[3] = {(const float*)d_in[2], (const float*)d_in[5], (const float*)d_in[8]};
    const float* Wr[3] = {(const float*)d_in[3], (const float*)d_in[6], (const float*)d_in[9]};
    const float* bl[3] = {(const float*)d_in[4], (const float*)d_in[7], (const float*)d_in[10]};
    const float* Wh = (const float*)d_in[11];
    const float* bh = (const float*)d_in[12];
    float* out = (float*)d_out;

    cudaFuncSetAttribute(gemm_kernel, cudaFuncAttributeMaxDynamicSharedMemorySize,
                         GEMM_SMEM_BYTES);

    void *pA, *pB, *pAgg;
    cudaGetSymbolAddress(&pA, g_bufA);
    cudaGetSymbolAddress(&pB, g_bufB);
    cudaGetSymbolAddress(&pAgg, g_agg);
    float* bufA = (float*)pA;
    float* bufB = (float*)pB;
    float* agg  = (float*)pAgg;

    // CSR build
    zero_init_kernel<<<(N_NODES + 255) / 256, 256>>>();
    detect_kernel<<<1, 256>>>((const unsigned*)ei);
    deg_kernel<<<(N_EDGES + 255) / 256, 256>>>(ei);
    bsum_kernel<<<NSCAN_BLOCKS, SCAN_BLK>>>();
    bscan_kernel<<<1, 128>>>();
    scatter_scan_kernel<<<NSCAN_BLOCKS, SCAN_BLK>>>();
    fill_kernel<<<(N_EDGES + 255) / 256, 256>>>(ei);

    const int warp_grid = (N_NODES * 32 + 255) / 256;
    const int gemm_grid = (N_NODES + GEMM_BM - 1) / GEMM_BM;

    const float* Hin = x;
    float* layer_out[3] = {bufA, bufB, bufA};
    for (int l = 0; l < 3; l++) {
        agg_kernel<<<warp_grid, 256>>>(Hin, agg);
        gemm_kernel<<<gemm_grid, GEMM_THREADS, GEMM_SMEM_BYTES>>>(
            agg, Hin, Wl[l], Wr[l], bl[l], layer_out[l]);
        Hin = layer_out[l];
    }
    head_kernel<<<warp_grid, 256>>>(Hin, Wh, bh, out);
}